// round 13
// baseline (speedup 1.0000x reference)
#include <cuda_runtime.h>
#include <cuda_fp16.h>
#include <math.h>
#include <stdint.h>

// ---------------- problem constants ----------------
#define NL   4
#define NB   64
#define NQ   4
#define NS   512
#define PSZ  16
#define NP   32
#define DM   2048
#define NH   32
#define NKV  8
#define HD   64
#define DFF  4096
#define NV   32000
#define NPAGES (NB*NP)
#define NT   (NB*NQ)      // 256 tokens
#define REPS 1e-5f

#define NQKV 3072         // 2048 q | 512 k | 512 v
#define NGU  8192         // 4096 gate | 4096 up

// ---------------- scratch ----------------
__device__ float  g_hidden[NT*DM];
__device__ float  g_qkv   [NT*NQKV];
__device__ float  g_gu    [NT*NGU];
__device__ float  g_part  [4ull*NT*NQKV];    // split-K partials
// fp16 hi/lo pre-split activation buffers (GEMM A operands)
__device__ __half g_hn_h [NT*DM],    g_hn_l [NT*DM];
__device__ __half g_hid_h[NT*DM],    g_hid_l[NT*DM];
__device__ __half g_ao_h [NT*NH*HD], g_ao_l [NT*NH*HD];
__device__ __half g_gd_h [NT*DFF],   g_gd_l [NT*DFF];

__device__ __forceinline__ void split16(float x, __half& h, __half& l) {
    h = __float2half_rn(x);
    l = __float2half_rn(x - __half2float(h));
}

// ---------------- embedding gather ----------------
__global__ void embed_kernel(const float* __restrict__ embed,
                             const int* __restrict__ ids,
                             float* __restrict__ out) {
    int t = blockIdx.x;
    int id = ids[t];
    const float4* src = (const float4*)(embed + (size_t)id * DM);
    float4* dst = (float4*)(out + (size_t)t * DM);
    for (int i = threadIdx.x; i < DM/4; i += blockDim.x) dst[i] = src[i];
}

// ---------------- rmsnorm -> split fp16 output ----------------
__global__ void __launch_bounds__(256) rmsnorm_kernel(const float* __restrict__ x,
                                                      const float* __restrict__ w,
                                                      __half* __restrict__ yh,
                                                      __half* __restrict__ yl) {
    int t = blockIdx.x;
    const float* xr = x + (size_t)t * DM;
    float ss = 0.f;
    for (int i = threadIdx.x; i < DM; i += 256) { float v = xr[i]; ss += v * v; }
    __shared__ float red[8];
    for (int o = 16; o; o >>= 1) ss += __shfl_xor_sync(~0u, ss, o);
    if ((threadIdx.x & 31) == 0) red[threadIdx.x >> 5] = ss;
    __syncthreads();
    if (threadIdx.x < 8) {
        float v = red[threadIdx.x];
        for (int o = 4; o; o >>= 1) v += __shfl_xor_sync(0xff, v, o);
        if (threadIdx.x == 0) red[0] = v;
    }
    __syncthreads();
    float inv = rsqrtf(red[0] / (float)DM + REPS);
    for (int i = threadIdx.x; i < DM; i += 256) {
        float v = xr[i] * inv * w[i];
        __half h, l; split16(v, h, l);
        yh[(size_t)t * DM + i] = h;
        yl[(size_t)t * DM + i] = l;
    }
}

// ---------------- mma helpers ----------------
__device__ __forceinline__ uint32_t h2bits(__half2 h) {
    return *reinterpret_cast<uint32_t*>(&h);
}
__device__ __forceinline__ void ldsm4(uint32_t* r, uint32_t addr) {
    asm volatile("ldmatrix.sync.aligned.m8n8.x4.shared.b16 {%0,%1,%2,%3}, [%4];"
                 : "=r"(r[0]), "=r"(r[1]), "=r"(r[2]), "=r"(r[3]) : "r"(addr));
}
__device__ __forceinline__ void mma16816(float* c, const uint32_t* a,
                                         uint32_t b0, uint32_t b1) {
    asm volatile(
        "mma.sync.aligned.m16n8k16.row.col.f32.f16.f16.f32 "
        "{%0,%1,%2,%3},{%4,%5,%6,%7},{%8,%9},{%0,%1,%2,%3};"
        : "+f"(c[0]), "+f"(c[1]), "+f"(c[2]), "+f"(c[3])
        : "r"(a[0]), "r"(a[1]), "r"(a[2]), "r"(a[3]), "r"(b0), "r"(b1));
}

// store one k-tile stage: A hi/lo direct (preconverted), B fp32->fp16 split
__device__ __forceinline__ void stage_store(
    uint32_t (*As)[128][12], uint32_t (*Bs)[64][12],
    const uint4& pah, const uint4& pal,
    float pb0, float pb1, float pb2, float pb3,
    int mA, int kqw, int nB, int ksw)
{
    *(uint4*)&As[0][mA][kqw] = pah;
    *(uint4*)&As[1][mA][kqw] = pal;

    __half2 h0 = __floats2half2_rn(pb0, pb1);
    __half2 h1 = __floats2half2_rn(pb2, pb3);
    __half2 l0 = __floats2half2_rn(pb0 - __low2float(h0), pb1 - __high2float(h0));
    __half2 l1 = __floats2half2_rn(pb2 - __low2float(h1), pb3 - __high2float(h1));
    Bs[0][nB][ksw]     = h2bits(h0);
    Bs[0][nB][ksw + 1] = h2bits(h1);
    Bs[1][nB][ksw]     = h2bits(l0);
    Bs[1][nB][ksw + 1] = h2bits(l1);
}

// ---------------- GEMM body: 128x64 tile, BK=16, double-buffered ------------
// 3-pass fp16 split: acc = Ah*Bh + Ah*Bl + Al*Bh
// Ah/Al: preconverted fp16 [*, lda].  B fp32 [klen rows, ldb].
__device__ __forceinline__ void gemm_body(
    const __half* __restrict__ Ah, const __half* __restrict__ Al, int lda,
    const float* __restrict__ B, int ldb,
    float* __restrict__ C, int ldc, const float* __restrict__ Res,
    int m0, int klen)
{
    __shared__ uint32_t AsU[2][2][128][12];   // [stage][hi/lo][row][kword]
    __shared__ uint32_t BsU[2][2][64][12];

    int tid  = threadIdx.x;
    int lane = tid & 31;
    int warp = tid >> 5;
    int wm = warp >> 1, wn = warp & 1;

    int mA  = tid >> 1;
    int kqw = (tid & 1) * 4;
    int nB  = tid >> 2;
    int ksw = (tid & 3) * 2;

    const char* ahp = (const char*)(Ah + (size_t)(m0 + mA) * lda + (tid & 1) * 8);
    const char* alp = (const char*)(Al + (size_t)(m0 + mA) * lda + (tid & 1) * 8);
    const float* bptr = B + nB;
    int nk = klen >> 4;

    float acc[2][4][4];
#pragma unroll
    for (int i = 0; i < 2; i++)
#pragma unroll
        for (int j = 0; j < 4; j++)
#pragma unroll
            for (int k = 0; k < 4; k++) acc[i][j][k] = 0.f;

    // prologue: load tile 0, store stage 0, load tile 1
    uint4 pah = *(const uint4*)ahp;
    uint4 pal = *(const uint4*)alp;
    float pb0 = bptr[(size_t)(ksw*2 + 0) * ldb];
    float pb1 = bptr[(size_t)(ksw*2 + 1) * ldb];
    float pb2 = bptr[(size_t)(ksw*2 + 2) * ldb];
    float pb3 = bptr[(size_t)(ksw*2 + 3) * ldb];
    stage_store(AsU[0], BsU[0], pah, pal, pb0, pb1, pb2, pb3, mA, kqw, nB, ksw);
    if (nk > 1) {
        pah = *(const uint4*)(ahp + 32);
        pal = *(const uint4*)(alp + 32);
        size_t kb = (size_t)(16 + ksw * 2);
        pb0 = bptr[(kb + 0) * ldb];
        pb1 = bptr[(kb + 1) * ldb];
        pb2 = bptr[(kb + 2) * ldb];
        pb3 = bptr[(kb + 3) * ldb];
    }
    __syncthreads();

    // ldmatrix addressing
    uint32_t as_base = (uint32_t)__cvta_generic_to_shared(&AsU[0][0][0][0]);
    uint32_t bs_base = (uint32_t)__cvta_generic_to_shared(&BsU[0][0][0][0]);
    int a_ro = ((lane >> 3) & 1) * 8 + (lane & 7);
    int a_ch = (lane >> 4) * 8;
    int b_ro = ((lane >> 4) & 1) * 8 + (lane & 7);
    int b_ch = ((lane >> 3) & 1) * 8;

    uint32_t aaddr[2][2], baddr[2][2];   // [hi/lo][tile]
#pragma unroll
    for (int b = 0; b < 2; b++) {
#pragma unroll
        for (int mt = 0; mt < 2; mt++)
            aaddr[b][mt] = as_base + (uint32_t)b * 6144u
                         + ((wm*32 + mt*16 + a_ro) * 12) * 4 + a_ch * 2;
#pragma unroll
        for (int nt2 = 0; nt2 < 2; nt2++)
            baddr[b][nt2] = bs_base + (uint32_t)b * 3072u
                          + ((wn*32 + nt2*16 + b_ro) * 12) * 4 + b_ch * 2;
    }

    for (int kt = 0; kt < nk; kt++) {
        int st = kt & 1;
        if (kt + 1 < nk)
            stage_store(AsU[st ^ 1], BsU[st ^ 1], pah, pal, pb0, pb1, pb2, pb3,
                        mA, kqw, nB, ksw);
        if (kt + 2 < nk) {
            pah = *(const uint4*)(ahp + (size_t)(kt + 2) * 32);
            pal = *(const uint4*)(alp + (size_t)(kt + 2) * 32);
            size_t kb = (size_t)((kt + 2) * 16 + ksw * 2);
            pb0 = bptr[(kb + 0) * ldb];
            pb1 = bptr[(kb + 1) * ldb];
            pb2 = bptr[(kb + 2) * ldb];
            pb3 = bptr[(kb + 3) * ldb];
        }

        uint32_t aoff = (uint32_t)st * 12288u;
        uint32_t boff = (uint32_t)st * 6144u;
        uint32_t Ahf[2][4], Alf[2][4], Bhf[2][4], Blf[2][4];
        ldsm4(Ahf[0], aaddr[0][0] + aoff); ldsm4(Ahf[1], aaddr[0][1] + aoff);
        ldsm4(Bhf[0], baddr[0][0] + boff); ldsm4(Bhf[1], baddr[0][1] + boff);
#pragma unroll
        for (int mt = 0; mt < 2; mt++)
#pragma unroll
            for (int nt = 0; nt < 4; nt++)
                mma16816(acc[mt][nt], Ahf[mt], Bhf[nt>>1][(nt&1)*2], Bhf[nt>>1][(nt&1)*2+1]);

        ldsm4(Blf[0], baddr[1][0] + boff); ldsm4(Blf[1], baddr[1][1] + boff);
#pragma unroll
        for (int mt = 0; mt < 2; mt++)
#pragma unroll
            for (int nt = 0; nt < 4; nt++)
                mma16816(acc[mt][nt], Ahf[mt], Blf[nt>>1][(nt&1)*2], Blf[nt>>1][(nt&1)*2+1]);

        ldsm4(Alf[0], aaddr[1][0] + aoff); ldsm4(Alf[1], aaddr[1][1] + aoff);
#pragma unroll
        for (int mt = 0; mt < 2; mt++)
#pragma unroll
            for (int nt = 0; nt < 4; nt++)
                mma16816(acc[mt][nt], Alf[mt], Bhf[nt>>1][(nt&1)*2], Bhf[nt>>1][(nt&1)*2+1]);

        __syncthreads();
    }

    // epilogue
    int g = lane >> 2, t4 = lane & 3;
#pragma unroll
    for (int mt = 0; mt < 2; mt++) {
#pragma unroll
        for (int nt = 0; nt < 4; nt++) {
            int row = m0 + wm*32 + mt*16 + g;
            int col = wn*32 + nt*8 + t4*2;
            float* cp0 = C + (size_t)row * ldc + col;
            float* cp1 = cp0 + (size_t)8 * ldc;
            float2 v0 = make_float2(acc[mt][nt][0], acc[mt][nt][1]);
            float2 v1 = make_float2(acc[mt][nt][2], acc[mt][nt][3]);
            if (Res) {
                const float* r0 = Res + (size_t)row * ldc + col;
                const float* r1 = r0 + (size_t)8 * ldc;
                v0.x += r0[0]; v0.y += r0[1];
                v1.x += r1[0]; v1.y += r1[1];
            }
            *(float2*)cp0 = v0;
            *(float2*)cp1 = v1;
        }
    }
}

// ---------------- GEMM wrappers ----------------
__global__ void __launch_bounds__(256) gemm_k(const __half* __restrict__ Ah,
                                              const __half* __restrict__ Al, int lda,
                                              const float* __restrict__ B,
                                              float* __restrict__ C,
                                              const float* __restrict__ Res,
                                              int N, int klen) {
    int s = blockIdx.z;
    int m0 = blockIdx.y * 128;
    int n0 = blockIdx.x * 64;
    const __half* Aho = Ah + (size_t)s * klen;
    const __half* Alo = Al + (size_t)s * klen;
    const float* Bo = B + (size_t)s * klen * N + n0;
    float* Cout; const float* R;
    if (gridDim.z == 1) { Cout = C + n0; R = Res ? Res + n0 : nullptr; }
    else { Cout = C + (size_t)s * NT * N + n0; R = nullptr; }
    gemm_body(Aho, Alo, lda, Bo, N, Cout, N, R, m0, klen);
}

// fused qkv: grid (48, 2, 4), klen=512, partial [s][NT][3072]
__global__ void __launch_bounds__(256) gemm_qkv(const __half* __restrict__ Ah,
                                                const __half* __restrict__ Al,
                                                const float* __restrict__ Bq,
                                                const float* __restrict__ Bk,
                                                const float* __restrict__ Bv,
                                                float* __restrict__ part) {
    int bx = blockIdx.x, s = blockIdx.z;
    int m0 = blockIdx.y * 128;
    const float* B; int ldb, nloc;
    if (bx < 32)      { B = Bq; ldb = 2048; nloc = bx * 64; }
    else if (bx < 40) { B = Bk; ldb = 512;  nloc = (bx - 32) * 64; }
    else              { B = Bv; ldb = 512;  nloc = (bx - 40) * 64; }
    const __half* Aho = Ah + (size_t)s * 512;
    const __half* Alo = Al + (size_t)s * 512;
    const float* Bo = B + (size_t)s * 512 * ldb + nloc;
    float* Cout = part + (size_t)s * NT * NQKV + bx * 64;
    gemm_body(Aho, Alo, DM, Bo, ldb, Cout, NQKV, nullptr, m0, 512);
}

// fused gate|up: grid (128, 2, 1), direct write into gu, klen=2048
__global__ void __launch_bounds__(256) gemm_gu(const __half* __restrict__ Ah,
                                               const __half* __restrict__ Al,
                                               const float* __restrict__ Bg,
                                               const float* __restrict__ Bu,
                                               float* __restrict__ gu) {
    int bx = blockIdx.x;
    int m0 = blockIdx.y * 128;
    const float* Bo; float* Cout;
    if (bx < 64) { Bo = Bg + bx * 64;        Cout = gu + bx * 64; }
    else         { Bo = Bu + (bx - 64) * 64; Cout = gu + DFF + (bx - 64) * 64; }
    gemm_body(Ah, Al, DM, Bo, DFF, Cout, NGU, nullptr, m0, 2048);
}

// ---------------- split-K reduce (no residual; for qkv) ----------------
__global__ void __launch_bounds__(256) reduce_kernel(float* __restrict__ dst,
                                                     const float* __restrict__ part,
                                                     int total, int S) {
    int i = (blockIdx.x * 256 + threadIdx.x) * 4;
    if (i >= total) return;
    float4 v = make_float4(0.f, 0.f, 0.f, 0.f);
    for (int s = 0; s < S; s++) {
        float4 p = *(const float4*)(part + (size_t)s * total + i);
        v.x += p.x; v.y += p.y; v.z += p.z; v.w += p.w;
    }
    *(float4*)(dst + i) = v;
}

// -------- fused: hid += sum(part); split(hid); hn = rmsnorm(hid,w) split ----
__global__ void __launch_bounds__(256) reduce_norm_kernel(
    float* __restrict__ hid, const float* __restrict__ part,
    const float* __restrict__ w,
    __half* __restrict__ hnh, __half* __restrict__ hnl,
    __half* __restrict__ hdh, __half* __restrict__ hdl) {
    int t = blockIdx.x;
    int tid = threadIdx.x;
    float4* hrow = (float4*)(hid + (size_t)t * DM);
    float4 v[2];
    float ss = 0.f;
#pragma unroll
    for (int j = 0; j < 2; j++) {
        int idx = tid + j * 256;
        float4 a = hrow[idx];
#pragma unroll
        for (int s = 0; s < 4; s++) {
            float4 p = *(const float4*)(part + ((size_t)s * NT + t) * DM + idx * 4);
            a.x += p.x; a.y += p.y; a.z += p.z; a.w += p.w;
        }
        hrow[idx] = a;
        v[j] = a;
        ss += a.x*a.x + a.y*a.y + a.z*a.z + a.w*a.w;
    }
    __shared__ float red[8];
    for (int o = 16; o; o >>= 1) ss += __shfl_xor_sync(~0u, ss, o);
    if ((tid & 31) == 0) red[tid >> 5] = ss;
    __syncthreads();
    if (tid < 8) {
        float x = red[tid];
        for (int o = 4; o; o >>= 1) x += __shfl_xor_sync(0xff, x, o);
        if (tid == 0) red[0] = x;
    }
    __syncthreads();
    float inv = rsqrtf(red[0] / (float)DM + REPS);
#pragma unroll
    for (int j = 0; j < 2; j++) {
        int idx = tid + j * 256;
        float4 wv = *(const float4*)(w + idx * 4);
        float hv[4] = {v[j].x, v[j].y, v[j].z, v[j].w};
        float wa[4] = {wv.x, wv.y, wv.z, wv.w};
#pragma unroll
        for (int e = 0; e < 4; e++) {
            size_t o = (size_t)t * DM + idx * 4 + e;
            __half h, l;
            split16(hv[e], h, l);
            hdh[o] = h; hdl[o] = l;
            float nv = hv[e] * inv * wa[e];
            split16(nv, h, l);
            hnh[o] = h; hnl[o] = l;
        }
    }
}

// ---------------- RoPE on fused qkv buffer ----------------
__global__ void rope_kernel(float* __restrict__ qkv) {
    int idx = blockIdx.x * blockDim.x + threadIdx.x;
    const int NQE = NT * NH  * 32;
    const int NKE = NT * NKV * 32;
    float* base; int d, pos;
    if (idx < NQE) {
        d = idx & 31;
        int h = (idx >> 5) % NH;
        int t = idx / (32 * NH);
        pos = NS + (t % NQ);
        base = qkv + (size_t)t * NQKV + h * HD;
    } else if (idx < NQE + NKE) {
        int j = idx - NQE;
        d = j & 31;
        int h = (j >> 5) % NKV;
        int t = j / (32 * NKV);
        pos = NS + (t % NQ);
        base = qkv + (size_t)t * NQKV + 2048 + h * HD;
    } else return;
    float inv = powf(10000.0f, -(float)d * (1.0f / 32.0f));
    float ang = (float)pos * inv;
    float c = cosf(ang), s = sinf(ang);
    float x1 = base[d], x2 = base[d + 32];
    base[d]      = x1 * c - x2 * s;
    base[d + 32] = x2 * c + x1 * s;
}

// ---------------- fused paged attention (split fp16 output) ----------------
__global__ void __launch_bounds__(256) attn_kernel(
    const float* __restrict__ kc, const float* __restrict__ vc,
    const int* __restrict__ page_table, const int* __restrict__ req_id,
    const float* __restrict__ qkv,
    __half* __restrict__ aoh, __half* __restrict__ aol) {

    __shared__ float q_s[16 * 64];
    __shared__ float sc [16 * 520];
    __shared__ float tile[64 * 33];
    __shared__ float rowinv[16];
    __shared__ int pages[NP];

    int kvh = blockIdx.x, b = blockIdx.y;
    int tid = threadIdx.x;

    if (tid < NP) pages[tid] = page_table[req_id[b] * NP + tid];
    {
        int row = tid >> 4;
        int d0  = (tid & 15) * 4;
        int hp = row >> 2, qi = row & 3;
        float4 v = *(const float4*)(qkv + (size_t)(b*NQ + qi) * NQKV + (kvh*4 + hp) * HD + d0);
        *(float4*)(q_s + row * 64 + d0) = v;
    }
    __syncthreads();

    const float scale = 0.125f;
    int jj_l = tid >> 3;
    int f4i  = tid & 7;
    int jj_c = tid & 31;
    int rgrp = tid >> 5;

    for (int t0 = 0; t0 < 16; t0++) {
        int j = t0 * 32 + jj_l;
        int page = pages[j >> 4];
        const float* kr = kc + (((size_t)page * PSZ + (j & 15)) * NKV + kvh) * HD;
#pragma unroll
        for (int i = 0; i < 2; i++) {
            int d0 = (f4i + 8 * i) * 4;
            float4 v = *(const float4*)(kr + d0);
            tile[(d0+0)*33 + jj_l] = v.x;
            tile[(d0+1)*33 + jj_l] = v.y;
            tile[(d0+2)*33 + jj_l] = v.z;
            tile[(d0+3)*33 + jj_l] = v.w;
        }
        __syncthreads();
        float a0 = 0.f, a1 = 0.f;
        const float* q0 = q_s + rgrp * 64;
        const float* q1 = q_s + (rgrp + 8) * 64;
#pragma unroll
        for (int d = 0; d < 64; d++) {
            float kv = tile[d * 33 + jj_c];
            a0 += kv * q0[d];
            a1 += kv * q1[d];
        }
        sc[rgrp       * 520 + t0*32 + jj_c] = a0 * scale;
        sc[(rgrp + 8) * 520 + t0*32 + jj_c] = a1 * scale;
        __syncthreads();
    }
    if (tid < 64) {
        int hp = tid >> 4, qi = (tid >> 2) & 3, qj = tid & 3;
        int row = hp * 4 + qi;
        const float* kr = qkv + (size_t)(b*NQ + qj) * NQKV + 2048 + kvh * HD;
        const float* qr = q_s + row * 64;
        float a = 0.f;
#pragma unroll
        for (int d = 0; d < 64; d++) a += qr[d] * kr[d];
        sc[row * 520 + 512 + qj] = (qj <= qi) ? a * scale : -1e30f;
    }
    __syncthreads();

    {
        int w = tid >> 5, lane = tid & 31;
        for (int rr = 0; rr < 2; rr++) {
            int row = w * 2 + rr;
            float* srow = sc + row * 520;
            float m = -1e30f;
            for (int j = lane; j < 516; j += 32) m = fmaxf(m, srow[j]);
            for (int o = 16; o; o >>= 1) m = fmaxf(m, __shfl_xor_sync(~0u, m, o));
            float s = 0.f;
            for (int j = lane; j < 516; j += 32) {
                float p = expf(srow[j] - m);
                srow[j] = p;
                s += p;
            }
            for (int o = 16; o; o >>= 1) s += __shfl_xor_sync(~0u, s, o);
            if (lane == 0) rowinv[row] = 1.f / s;
        }
    }
    __syncthreads();

    int d = tid & 63, rbase = tid >> 6;
    float oacc[4] = {0.f, 0.f, 0.f, 0.f};
    for (int t0 = 0; t0 < 16; t0++) {
        int j = t0 * 32 + jj_l;
        int page = pages[j >> 4];
        const float* vr = vc + (((size_t)page * PSZ + (j & 15)) * NKV + kvh) * HD;
#pragma unroll
        for (int i = 0; i < 2; i++) {
            int d0 = (f4i + 8 * i) * 4;
            float4 v = *(const float4*)(vr + d0);
            tile[(d0+0)*33 + jj_l] = v.x;
            tile[(d0+1)*33 + jj_l] = v.y;
            tile[(d0+2)*33 + jj_l] = v.z;
            tile[(d0+3)*33 + jj_l] = v.w;
        }
        __syncthreads();
#pragma unroll
        for (int jj = 0; jj < 32; jj++) {
            float vv = tile[d * 33 + jj];
            int jc = t0 * 32 + jj;
            oacc[0] += sc[(rbase     ) * 520 + jc] * vv;
            oacc[1] += sc[(rbase +  4) * 520 + jc] * vv;
            oacc[2] += sc[(rbase +  8) * 520 + jc] * vv;
            oacc[3] += sc[(rbase + 12) * 520 + jc] * vv;
        }
        __syncthreads();
    }
#pragma unroll
    for (int qj = 0; qj < 4; qj++) {
        float vv = qkv[(size_t)(b*NQ + qj) * NQKV + 2560 + kvh * HD + d];
        oacc[0] += sc[(rbase     ) * 520 + 512 + qj] * vv;
        oacc[1] += sc[(rbase +  4) * 520 + 512 + qj] * vv;
        oacc[2] += sc[(rbase +  8) * 520 + 512 + qj] * vv;
        oacc[3] += sc[(rbase + 12) * 520 + 512 + qj] * vv;
    }
#pragma unroll
    for (int r = 0; r < 4; r++) {
        int row = rbase + r * 4;
        int hp = row >> 2, qi = row & 3;
        float val = oacc[r] * rowinv[row];
        size_t o = ((size_t)(b*NQ + qi) * NH + (kvh*4 + hp)) * HD + d;
        __half h, l; split16(val, h, l);
        aoh[o] = h; aol[o] = l;
    }
}

// ---------------- silu(gate) * up -> split fp16 output ----------------
__global__ void silu_mul_kernel(const float* __restrict__ gu,
                                __half* __restrict__ gdh,
                                __half* __restrict__ gdl) {
    int i = blockIdx.x * blockDim.x + threadIdx.x;
    if (i < NT * DFF) {
        int row = i / DFF, c = i % DFF;
        float x = gu[(size_t)row * NGU + c];
        float u = gu[(size_t)row * NGU + DFF + c];
        float v = (x / (1.f + expf(-x))) * u;
        __half h, l; split16(v, h, l);
        gdh[i] = h; gdl[i] = l;
    }
}

// ---------------- host orchestration ----------------
extern "C" void kernel_launch(void* const* d_in, const int* in_sizes, int n_in,
                              void* d_out, int out_size) {
    const int*   input_ids  = (const int*)  d_in[0];
    const int*   req_id     = (const int*)  d_in[1];
    const int*   page_table = (const int*)  d_in[2];
    const float* embed      = (const float*)d_in[3];
    const float* w_in_ln    = (const float*)d_in[4];
    const float* wq         = (const float*)d_in[5];
    const float* wk         = (const float*)d_in[6];
    const float* wv         = (const float*)d_in[7];
    const float* wo         = (const float*)d_in[8];
    const float* w_post_ln  = (const float*)d_in[9];
    const float* w_gate     = (const float*)d_in[10];
    const float* w_up       = (const float*)d_in[11];
    const float* w_down     = (const float*)d_in[12];
    const float* k_cache    = (const float*)d_in[13];
    const float* v_cache    = (const float*)d_in[14];
    const float* lm_head    = (const float*)d_in[15];
    float* out = (float*)d_out;

    float *hid, *qkvb, *gu, *part;
    __half *hnh, *hnl, *hdh, *hdl, *aoh, *aol, *gdh, *gdl;
    cudaGetSymbolAddress((void**)&hid,  g_hidden);
    cudaGetSymbolAddress((void**)&qkvb, g_qkv);
    cudaGetSymbolAddress((void**)&gu,   g_gu);
    cudaGetSymbolAddress((void**)&part, g_part);
    cudaGetSymbolAddress((void**)&hnh,  g_hn_h);
    cudaGetSymbolAddress((void**)&hnl,  g_hn_l);
    cudaGetSymbolAddress((void**)&hdh,  g_hid_h);
    cudaGetSymbolAddress((void**)&hdl,  g_hid_l);
    cudaGetSymbolAddress((void**)&aoh,  g_ao_h);
    cudaGetSymbolAddress((void**)&aol,  g_ao_l);
    cudaGetSymbolAddress((void**)&gdh,  g_gd_h);
    cudaGetSymbolAddress((void**)&gdl,  g_gd_l);

    embed_kernel<<<NT, 256>>>(embed, input_ids, hid);
    rmsnorm_kernel<<<NT, 256>>>(hid, w_in_ln, hnh, hnl);   // layer 0 input norm

    for (int l = 0; l < NL; l++) {
        const float* wq_l = wq + (size_t)l * DM * (NH * HD);
        const float* wk_l = wk + (size_t)l * DM * (NKV * HD);
        const float* wv_l = wv + (size_t)l * DM * (NKV * HD);
        const float* wo_l = wo + (size_t)l * (NH * HD) * DM;
        const float* wg_l = w_gate + (size_t)l * DM * DFF;
        const float* wu_l = w_up   + (size_t)l * DM * DFF;
        const float* wd_l = w_down + (size_t)l * DFF * DM;
        const float* kc_l = k_cache + (size_t)l * NPAGES * PSZ * NKV * HD;
        const float* vc_l = v_cache + (size_t)l * NPAGES * PSZ * NKV * HD;
        const float* w_next = (l + 1 < NL) ? (w_in_ln + (size_t)(l + 1) * DM)
                                           : w_in_ln;   // dummy (hn unused after)

        gemm_qkv<<<dim3(48, 2, 4), 256>>>(hnh, hnl, wq_l, wk_l, wv_l, part);
        reduce_kernel<<<(NT*NQKV)/1024, 256>>>(qkvb, part, NT*NQKV, 4);

        rope_kernel<<<(NT*NH*32 + NT*NKV*32) / 256, 256>>>(qkvb);
        attn_kernel<<<dim3(NKV, NB), 256>>>(kc_l, vc_l, page_table, req_id, qkvb,
                                            aoh, aol);

        gemm_k<<<dim3(32, 2, 4), 256>>>(aoh, aol, NH*HD, wo_l, part, nullptr, DM, 512);
        reduce_norm_kernel<<<NT, 256>>>(hid, part, w_post_ln + (size_t)l * DM,
                                        hnh, hnl, hdh, hdl);

        gemm_gu<<<dim3(128, 2, 1), 256>>>(hnh, hnl, wg_l, wu_l, gu);
        silu_mul_kernel<<<(NT * DFF + 255) / 256, 256>>>(gu, gdh, gdl);

        gemm_k<<<dim3(32, 2, 4), 256>>>(gdh, gdl, DFF, wd_l, part, nullptr, DM, 1024);
        reduce_norm_kernel<<<NT, 256>>>(hid, part, w_next, hnh, hnl, hdh, hdl);
    }

    gemm_k<<<dim3(NV/64, 2, 1), 256>>>(hdh, hdl, DM, lm_head, out, nullptr, NV, 2048);
}